// round 1
// baseline (speedup 1.0000x reference)
#include <cuda_runtime.h>
#include <cuda_bf16.h>
#include <cstdint>

// Problem constants
// B=4, S=2048, D_MODEL=1024, H=16, DK=64, M = B*S = 8192
#define MB 4
#define SS 2048
#define DM 1024
#define NH 16
#define DK 64
#define MROWS 8192

// Scratch (allocation-free: __device__ globals)
__device__ float g_Qh[(size_t)MROWS * DM];  // [B,H,S,DK]
__device__ float g_Kh[(size_t)MROWS * DM];
__device__ float g_Vh[(size_t)MROWS * DM];
__device__ float g_AO[(size_t)MROWS * DM];  // attention output, [B,S,DM]

// ---------------------------------------------------------------------------
// GEMM: C = A[M=8192,K=1024] @ W^T (W is [N=1024,K=1024] row-major) + bias
// Tiling: 64x64x16, 256 threads, 4x4 microtile per thread.
// SPLIT=true  -> write head-split layout [B,H,S,DK]
// SPLIT=false -> write plain [M,N]
// ---------------------------------------------------------------------------
template <bool SPLIT>
__global__ __launch_bounds__(256)
void gemm_bias_kernel(const float* __restrict__ A,
                      const float* __restrict__ W,
                      const float* __restrict__ bias,
                      float* __restrict__ C) {
    __shared__ float As[16][68];   // rows padded to 68 floats -> 272B (16B aligned)
    __shared__ float Bs[16][68];

    const int lt = threadIdx.x;            // 0..255
    const int m0 = blockIdx.y * 64;
    const int n0 = blockIdx.x * 64;

    const int lm = lt >> 2;                // 0..63 (row within tile for loads)
    const int lk = (lt & 3) << 2;          // {0,4,8,12}

    const int tx = lt & 15;                // col group
    const int ty = lt >> 4;                // row group

    float acc[4][4];
#pragma unroll
    for (int i = 0; i < 4; i++)
#pragma unroll
        for (int j = 0; j < 4; j++) acc[i][j] = 0.f;

    for (int k0 = 0; k0 < 1024; k0 += 16) {
        float4 a4 = *(const float4*)(A + (size_t)(m0 + lm) * 1024 + k0 + lk);
        float4 b4 = *(const float4*)(W + (size_t)(n0 + lm) * 1024 + k0 + lk);
        As[lk + 0][lm] = a4.x; As[lk + 1][lm] = a4.y;
        As[lk + 2][lm] = a4.z; As[lk + 3][lm] = a4.w;
        Bs[lk + 0][lm] = b4.x; Bs[lk + 1][lm] = b4.y;
        Bs[lk + 2][lm] = b4.z; Bs[lk + 3][lm] = b4.w;
        __syncthreads();
#pragma unroll
        for (int k = 0; k < 16; k++) {
            float4 av = *(const float4*)&As[k][ty << 2];
            float4 bv = *(const float4*)&Bs[k][tx << 2];
            float af[4] = {av.x, av.y, av.z, av.w};
            float bf[4] = {bv.x, bv.y, bv.z, bv.w};
#pragma unroll
            for (int i = 0; i < 4; i++)
#pragma unroll
                for (int j = 0; j < 4; j++)
                    acc[i][j] = fmaf(af[i], bf[j], acc[i][j]);
        }
        __syncthreads();
    }

#pragma unroll
    for (int i = 0; i < 4; i++) {
        const int row = m0 + (ty << 2) + i;
#pragma unroll
        for (int j = 0; j < 4; j++) {
            const int col = n0 + (tx << 2) + j;
            const float v = acc[i][j] + bias[col];
            if (SPLIT) {
                const int bb = row >> 11;        // row / 2048
                const int s  = row & 2047;
                const int h  = col >> 6;         // col / 64
                const int d  = col & 63;
                C[(((size_t)bb * NH + h) * SS + s) * DK + d] = v;
            } else {
                C[(size_t)row * 1024 + col] = v;
            }
        }
    }
}

// ---------------------------------------------------------------------------
// Flash-style attention, fp32.
// Grid: (S/64, B*H). Block: 64 threads, one query row per thread.
// q and o live in registers; K/V tiles in smem (inner reads are warp-broadcast);
// per-tile scores parked in Ssh[j][tid] (lane-indexed -> conflict-free) so the
// online-softmax rescale happens once per 64-key tile.
// ---------------------------------------------------------------------------
__global__ __launch_bounds__(64)
void attn_kernel(const float* __restrict__ Qh,
                 const float* __restrict__ Kh,
                 const float* __restrict__ Vh,
                 float* __restrict__ AO) {
    __shared__ float Ksh[64 * 64];
    __shared__ float Vsh[64 * 64];
    __shared__ float Ssh[64 * 64];   // [j][tid]

    const int tid = threadIdx.x;
    const int bh  = blockIdx.y;          // 0..63 (b*16 + h)
    const int q0  = blockIdx.x * 64;
    const size_t base = (size_t)bh * SS * DK;

    // Load this thread's query row into registers
    float q[64];
    {
        const float4* Qg4 = (const float4*)(Qh + base + (size_t)(q0 + tid) * DK);
#pragma unroll
        for (int d4 = 0; d4 < 16; d4++) {
            float4 t = Qg4[d4];
            q[4 * d4 + 0] = t.x; q[4 * d4 + 1] = t.y;
            q[4 * d4 + 2] = t.z; q[4 * d4 + 3] = t.w;
        }
    }

    float o[64];
#pragma unroll
    for (int d = 0; d < 64; d++) o[d] = 0.f;
    float mrun = -1e30f;
    float lrun = 0.f;

    float4* Ksh4 = (float4*)Ksh;
    float4* Vsh4 = (float4*)Vsh;

    for (int k0 = 0; k0 < SS; k0 += 64) {
        const float4* Kg4 = (const float4*)(Kh + base + (size_t)k0 * DK);
        const float4* Vg4 = (const float4*)(Vh + base + (size_t)k0 * DK);
        __syncthreads();   // previous tile fully consumed
#pragma unroll
        for (int i = 0; i < 16; i++) {
            int f = i * 64 + tid;          // coalesced float4 index
            Ksh4[f] = Kg4[f];
            Vsh4[f] = Vg4[f];
        }
        __syncthreads();

        // Pass 1: scores for this thread's row vs 64 keys
        float tmax = -1e30f;
        for (int j = 0; j < 64; j++) {
            float a0 = 0.f, a1 = 0.f, a2 = 0.f, a3 = 0.f;
#pragma unroll
            for (int d4 = 0; d4 < 16; d4++) {
                float4 kk = Ksh4[j * 16 + d4];   // broadcast across lanes
                a0 = fmaf(q[4 * d4 + 0], kk.x, a0);
                a1 = fmaf(q[4 * d4 + 1], kk.y, a1);
                a2 = fmaf(q[4 * d4 + 2], kk.z, a2);
                a3 = fmaf(q[4 * d4 + 3], kk.w, a3);
            }
            float sc = ((a0 + a1) + (a2 + a3)) * 0.125f;   // 1/sqrt(64)
            tmax = fmaxf(tmax, sc);
            Ssh[j * 64 + tid] = sc;        // bank = tid -> conflict-free
        }

        // Online softmax update, rescale once per tile
        const float mnew = fmaxf(mrun, tmax);
        const float corr = __expf(mrun - mnew);
        mrun = mnew;
        lrun *= corr;
#pragma unroll
        for (int d = 0; d < 64; d++) o[d] *= corr;

        // Pass 2: accumulate P @ V
        for (int j = 0; j < 64; j++) {
            float p = __expf(Ssh[j * 64 + tid] - mrun);
            lrun += p;
#pragma unroll
            for (int d4 = 0; d4 < 16; d4++) {
                float4 vv = Vsh4[j * 16 + d4];   // broadcast across lanes
                o[4 * d4 + 0] = fmaf(p, vv.x, o[4 * d4 + 0]);
                o[4 * d4 + 1] = fmaf(p, vv.y, o[4 * d4 + 1]);
                o[4 * d4 + 2] = fmaf(p, vv.z, o[4 * d4 + 2]);
                o[4 * d4 + 3] = fmaf(p, vv.w, o[4 * d4 + 3]);
            }
        }
    }

    // Write [B,S,DM] for the output projection
    const float inv = 1.f / lrun;
    const int bb = bh >> 4;
    const int h  = bh & 15;
    float4* out4 = (float4*)(AO + ((size_t)(bb * SS + q0 + tid)) * DM + h * DK);
#pragma unroll
    for (int d4 = 0; d4 < 16; d4++) {
        out4[d4] = make_float4(o[4 * d4 + 0] * inv, o[4 * d4 + 1] * inv,
                               o[4 * d4 + 2] * inv, o[4 * d4 + 3] * inv);
    }
}

// ---------------------------------------------------------------------------
// Launch: 3 projection GEMMs -> attention -> output GEMM
// Inputs (metadata order): q,k,v,Wq,bq,Wk,bk,Wv,bv,Wo,bo
// ---------------------------------------------------------------------------
extern "C" void kernel_launch(void* const* d_in, const int* in_sizes, int n_in,
                              void* d_out, int out_size) {
    const float* q  = (const float*)d_in[0];
    const float* k  = (const float*)d_in[1];
    const float* v  = (const float*)d_in[2];
    const float* Wq = (const float*)d_in[3];
    const float* bq = (const float*)d_in[4];
    const float* Wk = (const float*)d_in[5];
    const float* bk = (const float*)d_in[6];
    const float* Wv = (const float*)d_in[7];
    const float* bv = (const float*)d_in[8];
    const float* Wo = (const float*)d_in[9];
    const float* bo = (const float*)d_in[10];

    void* p;
    cudaGetSymbolAddress(&p, g_Qh); float* Qh = (float*)p;
    cudaGetSymbolAddress(&p, g_Kh); float* Kh = (float*)p;
    cudaGetSymbolAddress(&p, g_Vh); float* Vh = (float*)p;
    cudaGetSymbolAddress(&p, g_AO); float* AO = (float*)p;

    dim3 gemm_grid(DM / 64, MROWS / 64);   // (16, 128)

    gemm_bias_kernel<true><<<gemm_grid, 256>>>(q, Wq, bq, Qh);
    gemm_bias_kernel<true><<<gemm_grid, 256>>>(k, Wk, bk, Kh);
    gemm_bias_kernel<true><<<gemm_grid, 256>>>(v, Wv, bv, Vh);

    attn_kernel<<<dim3(SS / 64, MB * NH), 64>>>(Qh, Kh, Vh, AO);

    gemm_bias_kernel<false><<<gemm_grid, 256>>>(AO, Wo, bo, (float*)d_out);
}

// round 5
// speedup vs baseline: 4.5148x; 4.5148x over previous
#include <cuda_runtime.h>
#include <cstdint>

// Problem constants: B=4, S=2048, D_MODEL=1024, H=16, DK=64, M = B*S = 8192
#define MB 4
#define SS 2048
#define DM 1024
#define NH 16
#define DK 64
#define MROWS 8192

// Scratch (allocation-free: __device__ globals)
__device__ float g_Qh[(size_t)MROWS * DM];   // [B,H,S,DK] fp32
__device__ float g_Kh[(size_t)MROWS * DM];
__device__ float g_Vh[(size_t)MROWS * DM];
__device__ float g_AO[(size_t)MROWS * DM];   // [B,S,DM], tf32-rounded fp32
__device__ float g_cq[(size_t)MROWS * DM];   // tf32-rounded copies of inputs
__device__ float g_ck[(size_t)MROWS * DM];
__device__ float g_cv[(size_t)MROWS * DM];
__device__ float g_wq[(size_t)DM * DM];
__device__ float g_wk[(size_t)DM * DM];
__device__ float g_wv[(size_t)DM * DM];
__device__ float g_wo[(size_t)DM * DM];

// ---------------------------------------------------------------------------
// Helpers (base sm_103-legal only: mma.sync tf32 + cp.async)
// ---------------------------------------------------------------------------
__device__ __forceinline__ uint32_t f2tf32(float f) {
    uint32_t r;
    asm("cvt.rna.tf32.f32 %0, %1;" : "=r"(r) : "f"(f));
    return r;
}
__device__ __forceinline__ void mma_tf32(float* c, const uint32_t* a,
                                         const uint32_t* b) {
    asm volatile(
        "mma.sync.aligned.m16n8k8.row.col.f32.tf32.tf32.f32 "
        "{%0,%1,%2,%3}, {%4,%5,%6,%7}, {%8,%9}, {%0,%1,%2,%3};"
        : "+f"(c[0]), "+f"(c[1]), "+f"(c[2]), "+f"(c[3])
        : "r"(a[0]), "r"(a[1]), "r"(a[2]), "r"(a[3]), "r"(b[0]), "r"(b[1]));
}
__device__ __forceinline__ uint32_t smem_u32(const void* p) {
    uint32_t a;
    asm("{ .reg .u64 t; cvta.to.shared.u64 t, %1; cvt.u32.u64 %0, t; }"
        : "=r"(a) : "l"(p));
    return a;
}
__device__ __forceinline__ void cp16(uint32_t d, const void* s) {
    asm volatile("cp.async.cg.shared.global [%0], [%1], 16;" :: "r"(d), "l"(s));
}
#define CP_COMMIT() asm volatile("cp.async.commit_group;" ::: "memory")
#define CP_WAIT1()  asm volatile("cp.async.wait_group 1;" ::: "memory")

// ---------------------------------------------------------------------------
// Pre-pass: round fp32 -> nearest tf32-representable fp32 (rna)
// ---------------------------------------------------------------------------
__global__ void cvt_tf32_kernel(const float4* __restrict__ src,
                                float4* __restrict__ dst, int n4) {
    int i = blockIdx.x * 256 + threadIdx.x;
    if (i < n4) {
        float4 v = src[i];
        uint4 o;
        o.x = f2tf32(v.x); o.y = f2tf32(v.y);
        o.z = f2tf32(v.z); o.w = f2tf32(v.w);
        ((uint4*)dst)[i] = o;
    }
}

// ---------------------------------------------------------------------------
// tf32 mma.sync GEMM: C[8192,1024] = A @ W^T + bias.  W is [N,K] row-major.
// CTA 128x128, 4 warps (2x2), warp tile 64x64, KC=32, 3-stage cp.async.
// SMEM pitch 36 floats -> fragment loads hit 32 distinct banks.
// A and W must be pre-rounded to tf32.
// ---------------------------------------------------------------------------
#define PITCH 36
#define STW   (128 * PITCH)                  // floats per operand-stage
#define GEMM_SMEM_BYTES (6 * STW * 4)        // 110592 B

template <bool SPLIT>
__global__ __launch_bounds__(128)
void gemm_tc(const float* __restrict__ A, const float* __restrict__ W,
             const float* __restrict__ bias, float* __restrict__ C) {
    extern __shared__ float sm[];
    const int tid = threadIdx.x, lane = tid & 31, wid = tid >> 5;
    const int lr = lane >> 2, lc = lane & 3;
    const int wm = wid & 1, wn = wid >> 1;
    const int m0 = blockIdx.y * 128, n0 = blockIdx.x * 128;
    const uint32_t sa = smem_u32(sm);

    float c[4][8][4];
#pragma unroll
    for (int mf = 0; mf < 4; mf++)
#pragma unroll
        for (int nf = 0; nf < 8; nf++)
#pragma unroll
            for (int r = 0; r < 4; r++) c[mf][nf][r] = 0.f;

#define GEMM_LOAD_STAGE(st, t) do {                                           \
    const int _k0 = (t) * 32;                                                 \
    _Pragma("unroll")                                                         \
    for (int _i = 0; _i < 8; _i++) {                                          \
        int _idx = _i * 128 + tid, _row = _idx >> 3, _c4 = (_idx & 7) * 4;    \
        uint32_t _off = (uint32_t)(((st) * STW + _row * PITCH + _c4) * 4);    \
        cp16(sa + _off, A + (size_t)(m0 + _row) * DM + _k0 + _c4);            \
        cp16(sa + (uint32_t)(3 * STW * 4) + _off,                             \
             W + (size_t)(n0 + _row) * DM + _k0 + _c4);                       \
    }                                                                         \
} while (0)

    GEMM_LOAD_STAGE(0, 0); CP_COMMIT();
    GEMM_LOAD_STAGE(1, 1); CP_COMMIT();

    const int NT = DM / 32;   // 32 chunks
    for (int t = 0; t < NT; t++) {
        CP_WAIT1();
        __syncthreads();
        if (t + 2 < NT) GEMM_LOAD_STAGE((t + 2) % 3, t + 2);
        CP_COMMIT();   // empty group when nothing loaded keeps FIFO math valid

        const uint32_t* Au = (const uint32_t*)(sm + (t % 3) * STW);
        const uint32_t* Bu = (const uint32_t*)(sm + 3 * STW + (t % 3) * STW);
#pragma unroll
        for (int kk = 0; kk < 4; kk++) {
            uint32_t a[4][4], b[8][2];
#pragma unroll
            for (int mf = 0; mf < 4; mf++) {
                int rb = wm * 64 + mf * 16;
                a[mf][0] = Au[(rb + lr) * PITCH + kk * 8 + lc];
                a[mf][1] = Au[(rb + lr + 8) * PITCH + kk * 8 + lc];
                a[mf][2] = Au[(rb + lr) * PITCH + kk * 8 + lc + 4];
                a[mf][3] = Au[(rb + lr + 8) * PITCH + kk * 8 + lc + 4];
            }
#pragma unroll
            for (int nf = 0; nf < 8; nf++) {
                int nb = wn * 64 + nf * 8 + lr;
                b[nf][0] = Bu[nb * PITCH + kk * 8 + lc];
                b[nf][1] = Bu[nb * PITCH + kk * 8 + lc + 4];
            }
#pragma unroll
            for (int mf = 0; mf < 4; mf++)
#pragma unroll
                for (int nf = 0; nf < 8; nf++)
                    mma_tf32(c[mf][nf], a[mf], b[nf]);
        }
    }

    // Epilogue: C-frag (r, 2lc) / (r+8, 2lc) float2 stores + bias
#pragma unroll
    for (int mf = 0; mf < 4; mf++) {
#pragma unroll
        for (int h = 0; h < 2; h++) {
            const int row = m0 + wm * 64 + mf * 16 + lr + 8 * h;
#pragma unroll
            for (int nf = 0; nf < 8; nf++) {
                const int col = n0 + wn * 64 + nf * 8 + 2 * lc;
                float v0 = c[mf][nf][2 * h + 0] + bias[col];
                float v1 = c[mf][nf][2 * h + 1] + bias[col + 1];
                size_t off;
                if (SPLIT) {
                    int bb = row >> 11, s = row & 2047;
                    int hh = col >> 6, d = col & 63;
                    off = (((size_t)(bb * NH + hh) * SS + s) * DK) + d;
                } else {
                    off = (size_t)row * DM + col;
                }
                *(float2*)(C + off) = make_float2(v0, v1);
            }
        }
    }
}

// ---------------------------------------------------------------------------
// Tensor-core flash attention (tf32 mma.sync).
// Grid (S/128, B*H), 128 threads (4 warps). Warp owns 32 q-rows (2 m16 frags).
// Q frags register-resident (staged through Ksh twice). KV tile 64.
// Dynamic smem: Ksh pitch 68, Vsh pitch 72 (64-wide rows, conflict-free PV
// B-frag reads: bank = lc*8+lr = lane), Psh pitch 36 warp-private 32x32.
// ---------------------------------------------------------------------------
#define KP 68
#define VP 72
#define ATTN_SMEM_FLOATS (64 * KP + 64 * VP + 4 * 32 * PITCH)
#define ATTN_SMEM_BYTES  (ATTN_SMEM_FLOATS * 4)   // 54272 B

__global__ __launch_bounds__(128)
void attn_tc(const float* __restrict__ Qh, const float* __restrict__ Kh,
             const float* __restrict__ Vh, float* __restrict__ AO) {
    extern __shared__ float dynsm[];
    float* Ksh = dynsm;                    // 64*68 = 4352 floats (also Q staging)
    float* Vsh = dynsm + 64 * KP;          // 64*72 = 4608 floats
    float* Psh = dynsm + 64 * KP + 64 * VP; // 4*32*36 = 4608 floats

    const int tid = threadIdx.x, lane = tid & 31, wid = tid >> 5;
    const int lr = lane >> 2, lc = lane & 3;
    const int bh = blockIdx.y;
    const int q0 = blockIdx.x * 128;
    const size_t base = (size_t)bh * SS * DK;
    const uint32_t* Ku = (const uint32_t*)Ksh;
    const uint32_t* Vu = (const uint32_t*)Vsh;

    // ---- Stage Q (scaled by 1/sqrt(64), rna-rounded) into register frags ----
    uint32_t qa[2][8][4];
    for (int pass = 0; pass < 2; pass++) {
        __syncthreads();
#pragma unroll
        for (int i = 0; i < 8; i++) {
            int idx = i * 128 + tid, row = idx >> 4, f4 = (idx & 15) * 4;
            float4 qv = *(const float4*)(Qh + base +
                        (size_t)(q0 + pass * 64 + row) * DK + f4);
            uint32_t* d = (uint32_t*)&Ksh[row * KP + f4];
            d[0] = f2tf32(qv.x * 0.125f); d[1] = f2tf32(qv.y * 0.125f);
            d[2] = f2tf32(qv.z * 0.125f); d[3] = f2tf32(qv.w * 0.125f);
        }
        __syncthreads();
        if ((wid >> 1) == pass) {
            const int rb0 = (wid & 1) * 32;
#pragma unroll
            for (int mf = 0; mf < 2; mf++) {
                int rb = rb0 + mf * 16;
#pragma unroll
                for (int kk = 0; kk < 8; kk++) {
                    qa[mf][kk][0] = Ku[(rb + lr) * KP + kk * 8 + lc];
                    qa[mf][kk][1] = Ku[(rb + lr + 8) * KP + kk * 8 + lc];
                    qa[mf][kk][2] = Ku[(rb + lr) * KP + kk * 8 + lc + 4];
                    qa[mf][kk][3] = Ku[(rb + lr + 8) * KP + kk * 8 + lc + 4];
                }
            }
        }
    }

    float o[2][8][4];
#pragma unroll
    for (int mf = 0; mf < 2; mf++)
#pragma unroll
        for (int nf = 0; nf < 8; nf++)
#pragma unroll
            for (int r = 0; r < 4; r++) o[mf][nf][r] = 0.f;
    float mrow[2][2] = {{-1e30f, -1e30f}, {-1e30f, -1e30f}};
    float lrow[2][2] = {{0.f, 0.f}, {0.f, 0.f}};

    uint32_t* Pw = (uint32_t*)(Psh + wid * 32 * PITCH);

    for (int t = 0; t < SS / 64; t++) {
        __syncthreads();
#pragma unroll
        for (int i = 0; i < 8; i++) {
            int idx = i * 128 + tid, row = idx >> 4, f4 = (idx & 15) * 4;
            float4 kv = *(const float4*)(Kh + base + (size_t)(t * 64 + row) * DK + f4);
            uint32_t* kd = (uint32_t*)&Ksh[row * KP + f4];
            kd[0] = f2tf32(kv.x); kd[1] = f2tf32(kv.y);
            kd[2] = f2tf32(kv.z); kd[3] = f2tf32(kv.w);
            float4 vv = *(const float4*)(Vh + base + (size_t)(t * 64 + row) * DK + f4);
            uint32_t* vd = (uint32_t*)&Vsh[row * VP + f4];
            vd[0] = f2tf32(vv.x); vd[1] = f2tf32(vv.y);
            vd[2] = f2tf32(vv.z); vd[3] = f2tf32(vv.w);
        }
        __syncthreads();

        // ---- S = Q @ K^T ----
        float s[2][8][4];
#pragma unroll
        for (int mf = 0; mf < 2; mf++)
#pragma unroll
            for (int nf = 0; nf < 8; nf++)
#pragma unroll
                for (int r = 0; r < 4; r++) s[mf][nf][r] = 0.f;
#pragma unroll
        for (int kk = 0; kk < 8; kk++) {
            uint32_t b[8][2];
#pragma unroll
            for (int nf = 0; nf < 8; nf++) {
                int nb = nf * 8 + lr;
                b[nf][0] = Ku[nb * KP + kk * 8 + lc];
                b[nf][1] = Ku[nb * KP + kk * 8 + lc + 4];
            }
#pragma unroll
            for (int mf = 0; mf < 2; mf++)
#pragma unroll
                for (int nf = 0; nf < 8; nf++)
                    mma_tf32(s[mf][nf], qa[mf][kk], b[nf]);
        }

        // ---- Online softmax (rows r / r+8 per m-frag; quad covers 64 cols) ----
#pragma unroll
        for (int mf = 0; mf < 2; mf++) {
#pragma unroll
            for (int h = 0; h < 2; h++) {
                float tm = -1e30f;
#pragma unroll
                for (int nf = 0; nf < 8; nf++)
                    tm = fmaxf(tm, fmaxf(s[mf][nf][2 * h], s[mf][nf][2 * h + 1]));
                tm = fmaxf(tm, __shfl_xor_sync(0xffffffffu, tm, 1));
                tm = fmaxf(tm, __shfl_xor_sync(0xffffffffu, tm, 2));
                float mn = fmaxf(mrow[mf][h], tm);
                float corr = __expf(mrow[mf][h] - mn);
                mrow[mf][h] = mn;
                float rs = 0.f;
#pragma unroll
                for (int nf = 0; nf < 8; nf++) {
                    float p0 = __expf(s[mf][nf][2 * h] - mn);
                    float p1 = __expf(s[mf][nf][2 * h + 1] - mn);
                    s[mf][nf][2 * h] = p0; s[mf][nf][2 * h + 1] = p1;
                    rs += p0 + p1;
                    o[mf][nf][2 * h] *= corr; o[mf][nf][2 * h + 1] *= corr;
                }
                rs += __shfl_xor_sync(0xffffffffu, rs, 1);
                rs += __shfl_xor_sync(0xffffffffu, rs, 2);
                lrow[mf][h] = lrow[mf][h] * corr + rs;
            }
        }

        // ---- O += P @ V, two 32-key halves (P slice is 32x32, pitch 36) ----
#pragma unroll
        for (int half = 0; half < 2; half++) {
            __syncwarp();
#pragma unroll
            for (int mf = 0; mf < 2; mf++)
#pragma unroll
                for (int nfl = 0; nfl < 4; nfl++) {
                    int nf = half * 4 + nfl;
                    int r0 = mf * 16 + lr, col = nfl * 8 + 2 * lc;
                    Pw[r0 * PITCH + col]           = f2tf32(s[mf][nf][0]);
                    Pw[r0 * PITCH + col + 1]       = f2tf32(s[mf][nf][1]);
                    Pw[(r0 + 8) * PITCH + col]     = f2tf32(s[mf][nf][2]);
                    Pw[(r0 + 8) * PITCH + col + 1] = f2tf32(s[mf][nf][3]);
                }
            __syncwarp();
#pragma unroll
            for (int kk = 0; kk < 4; kk++) {
                uint32_t a[2][4], b[8][2];
#pragma unroll
                for (int mf = 0; mf < 2; mf++) {
                    int rb = mf * 16;
                    a[mf][0] = Pw[(rb + lr) * PITCH + kk * 8 + lc];
                    a[mf][1] = Pw[(rb + lr + 8) * PITCH + kk * 8 + lc];
                    a[mf][2] = Pw[(rb + lr) * PITCH + kk * 8 + lc + 4];
                    a[mf][3] = Pw[(rb + lr + 8) * PITCH + kk * 8 + lc + 4];
                }
                const int krow = half * 32 + kk * 8;
#pragma unroll
                for (int nf = 0; nf < 8; nf++) {
                    b[nf][0] = Vu[(krow + lc) * VP + nf * 8 + lr];
                    b[nf][1] = Vu[(krow + lc + 4) * VP + nf * 8 + lr];
                }
#pragma unroll
                for (int mf = 0; mf < 2; mf++)
#pragma unroll
                    for (int nf = 0; nf < 8; nf++)
                        mma_tf32(o[mf][nf], a[mf], b[nf]);
            }
        }
    }

    // ---- Epilogue: write AO [B,S,DM], tf32-rounded for the final GEMM ----
    const int bb = bh >> 4, hh = bh & 15;
#pragma unroll
    for (int mf = 0; mf < 2; mf++) {
#pragma unroll
        for (int h = 0; h < 2; h++) {
            float inv = 1.f / lrow[mf][h];
            int row = q0 + wid * 32 + mf * 16 + lr + 8 * h;
            float* dst = AO + ((size_t)bb * SS + row) * DM + hh * DK;
#pragma unroll
            for (int nf = 0; nf < 8; nf++) {
                int d = nf * 8 + 2 * lc;
                float2 w;
                w.x = __uint_as_float(f2tf32(o[mf][nf][2 * h] * inv));
                w.y = __uint_as_float(f2tf32(o[mf][nf][2 * h + 1] * inv));
                *(float2*)(dst + d) = w;
            }
        }
    }
}

// ---------------------------------------------------------------------------
// Launch
// ---------------------------------------------------------------------------
extern "C" void kernel_launch(void* const* d_in, const int* in_sizes, int n_in,
                              void* d_out, int out_size) {
    const float* q  = (const float*)d_in[0];
    const float* k  = (const float*)d_in[1];
    const float* v  = (const float*)d_in[2];
    const float* Wq = (const float*)d_in[3];
    const float* bq = (const float*)d_in[4];
    const float* Wk = (const float*)d_in[5];
    const float* bk = (const float*)d_in[6];
    const float* Wv = (const float*)d_in[7];
    const float* bv = (const float*)d_in[8];
    const float* Wo = (const float*)d_in[9];
    const float* bo = (const float*)d_in[10];

    void* p;
    cudaGetSymbolAddress(&p, g_Qh); float* Qh = (float*)p;
    cudaGetSymbolAddress(&p, g_Kh); float* Kh = (float*)p;
    cudaGetSymbolAddress(&p, g_Vh); float* Vh = (float*)p;
    cudaGetSymbolAddress(&p, g_AO); float* AO = (float*)p;
    cudaGetSymbolAddress(&p, g_cq); float* cq = (float*)p;
    cudaGetSymbolAddress(&p, g_ck); float* ck = (float*)p;
    cudaGetSymbolAddress(&p, g_cv); float* cv = (float*)p;
    cudaGetSymbolAddress(&p, g_wq); float* wq = (float*)p;
    cudaGetSymbolAddress(&p, g_wk); float* wk = (float*)p;
    cudaGetSymbolAddress(&p, g_wv); float* wv = (float*)p;
    cudaGetSymbolAddress(&p, g_wo); float* wo = (float*)p;

    cudaFuncSetAttribute(gemm_tc<true>,  cudaFuncAttributeMaxDynamicSharedMemorySize,
                         GEMM_SMEM_BYTES);
    cudaFuncSetAttribute(gemm_tc<false>, cudaFuncAttributeMaxDynamicSharedMemorySize,
                         GEMM_SMEM_BYTES);
    cudaFuncSetAttribute(attn_tc, cudaFuncAttributeMaxDynamicSharedMemorySize,
                         ATTN_SMEM_BYTES);

    const int n4in = MROWS * DM / 4;   // 2M float4s
    const int n4w  = DM * DM / 4;      // 256K float4s
    cvt_tf32_kernel<<<(n4in + 255) / 256, 256>>>((const float4*)q, (float4*)cq, n4in);
    cvt_tf32_kernel<<<(n4in + 255) / 256, 256>>>((const float4*)k, (float4*)ck, n4in);
    cvt_tf32_kernel<<<(n4in + 255) / 256, 256>>>((const float4*)v, (float4*)cv, n4in);
    cvt_tf32_kernel<<<(n4w + 255) / 256, 256>>>((const float4*)Wq, (float4*)wq, n4w);
    cvt_tf32_kernel<<<(n4w + 255) / 256, 256>>>((const float4*)Wk, (float4*)wk, n4w);
    cvt_tf32_kernel<<<(n4w + 255) / 256, 256>>>((const float4*)Wv, (float4*)wv, n4w);
    cvt_tf32_kernel<<<(n4w + 255) / 256, 256>>>((const float4*)Wo, (float4*)wo, n4w);

    dim3 gg(DM / 128, MROWS / 128);    // (8, 64)
    gemm_tc<true><<<gg, 128, GEMM_SMEM_BYTES>>>(cq, wq, bq, Qh);
    gemm_tc<true><<<gg, 128, GEMM_SMEM_BYTES>>>(ck, wk, bk, Kh);
    gemm_tc<true><<<gg, 128, GEMM_SMEM_BYTES>>>(cv, wv, bv, Vh);

    attn_tc<<<dim3(SS / 128, MB * NH), 128, ATTN_SMEM_BYTES>>>(Qh, Kh, Vh, AO);

    gemm_tc<false><<<gg, 128, GEMM_SMEM_BYTES>>>(AO, wo, bo, (float*)d_out);
}

// round 6
// speedup vs baseline: 4.8974x; 1.0847x over previous
#include <cuda_runtime.h>
#include <cstdint>

// Problem constants: B=4, S=2048, D_MODEL=1024, H=16, DK=64, M = B*S = 8192
#define MB 4
#define SS 2048
#define DM 1024
#define NH 16
#define DK 64
#define MROWS 8192

// Scratch (allocation-free: __device__ globals)
__device__ float g_Qh[(size_t)MROWS * DM];   // [B,H,S,DK] fp32
__device__ float g_Kh[(size_t)MROWS * DM];
__device__ float g_Vh[(size_t)MROWS * DM];
__device__ float g_AO[(size_t)MROWS * DM];   // [B,S,DM] fp32

// ---------------------------------------------------------------------------
// Helpers (base sm_103-legal only: mma.sync tf32 + cp.async)
// ---------------------------------------------------------------------------
__device__ __forceinline__ uint32_t f2tf32(float f) {
    uint32_t r;
    asm("cvt.rna.tf32.f32 %0, %1;" : "=r"(r) : "f"(f));
    return r;
}
__device__ __forceinline__ void mma_tf32(float* c, const uint32_t* a,
                                         const uint32_t* b) {
    asm volatile(
        "mma.sync.aligned.m16n8k8.row.col.f32.tf32.tf32.f32 "
        "{%0,%1,%2,%3}, {%4,%5,%6,%7}, {%8,%9}, {%0,%1,%2,%3};"
        : "+f"(c[0]), "+f"(c[1]), "+f"(c[2]), "+f"(c[3])
        : "r"(a[0]), "r"(a[1]), "r"(a[2]), "r"(a[3]), "r"(b[0]), "r"(b[1]));
}
__device__ __forceinline__ uint32_t smem_u32(const void* p) {
    uint32_t a;
    asm("{ .reg .u64 t; cvta.to.shared.u64 t, %1; cvt.u32.u64 %0, t; }"
        : "=r"(a) : "l"(p));
    return a;
}
__device__ __forceinline__ void cp16(uint32_t d, const void* s) {
    asm volatile("cp.async.cg.shared.global [%0], [%1], 16;" :: "r"(d), "l"(s));
}
#define CP_COMMIT() asm volatile("cp.async.commit_group;" ::: "memory")
#define CP_WAIT1()  asm volatile("cp.async.wait_group 1;" ::: "memory")
#define CP_WAIT0()  asm volatile("cp.async.wait_group 0;" ::: "memory")

// ---------------------------------------------------------------------------
// tf32 mma.sync GEMM: C[8192,1024] = A @ W^T + bias.  W is [N,K] row-major.
// CTA 128x128, 4 warps (2x2), warp tile 64x64, KC=32, 3-stage cp.async.
// Operands are RAW fp32 in smem; fragments are rna-rounded to tf32 in regs.
// grid.z selects one of up to 3 (A, W, bias, C) problem triplets.
// ---------------------------------------------------------------------------
#define PITCH 36
#define STW   (128 * PITCH)                  // floats per operand-stage
#define GEMM_SMEM_BYTES (6 * STW * 4)        // 110592 B

template <bool SPLIT>
__global__ __launch_bounds__(128)
void gemm_tc(const float* __restrict__ A0, const float* __restrict__ A1,
             const float* __restrict__ A2,
             const float* __restrict__ W0, const float* __restrict__ W1,
             const float* __restrict__ W2,
             const float* __restrict__ b0, const float* __restrict__ b1,
             const float* __restrict__ b2,
             float* __restrict__ C0, float* __restrict__ C1,
             float* __restrict__ C2) {
    extern __shared__ float sm[];
    const int z = blockIdx.z;
    const float* A    = (z == 0) ? A0 : (z == 1) ? A1 : A2;
    const float* W    = (z == 0) ? W0 : (z == 1) ? W1 : W2;
    const float* bias = (z == 0) ? b0 : (z == 1) ? b1 : b2;
    float*       C    = (z == 0) ? C0 : (z == 1) ? C1 : C2;

    const int tid = threadIdx.x, lane = tid & 31, wid = tid >> 5;
    const int lr = lane >> 2, lc = lane & 3;
    const int wm = wid & 1, wn = wid >> 1;
    const int m0 = blockIdx.y * 128, n0 = blockIdx.x * 128;
    const uint32_t sa = smem_u32(sm);

    float c[4][8][4];
#pragma unroll
    for (int mf = 0; mf < 4; mf++)
#pragma unroll
        for (int nf = 0; nf < 8; nf++)
#pragma unroll
            for (int r = 0; r < 4; r++) c[mf][nf][r] = 0.f;

#define GEMM_LOAD_STAGE(st, t) do {                                           \
    const int _k0 = (t) * 32;                                                 \
    _Pragma("unroll")                                                         \
    for (int _i = 0; _i < 8; _i++) {                                          \
        int _idx = _i * 128 + tid, _row = _idx >> 3, _c4 = (_idx & 7) * 4;    \
        uint32_t _off = (uint32_t)(((st) * STW + _row * PITCH + _c4) * 4);    \
        cp16(sa + _off, A + (size_t)(m0 + _row) * DM + _k0 + _c4);            \
        cp16(sa + (uint32_t)(3 * STW * 4) + _off,                             \
             W + (size_t)(n0 + _row) * DM + _k0 + _c4);                       \
    }                                                                         \
} while (0)

    GEMM_LOAD_STAGE(0, 0); CP_COMMIT();
    GEMM_LOAD_STAGE(1, 1); CP_COMMIT();

    const int NT = DM / 32;   // 32 chunks
    for (int t = 0; t < NT; t++) {
        CP_WAIT1();
        __syncthreads();
        if (t + 2 < NT) GEMM_LOAD_STAGE((t + 2) % 3, t + 2);
        CP_COMMIT();   // empty group when nothing loaded keeps FIFO math valid

        const float* Au = sm + (t % 3) * STW;
        const float* Bu = sm + 3 * STW + (t % 3) * STW;
#pragma unroll
        for (int kk = 0; kk < 4; kk++) {
            uint32_t a[4][4], b[8][2];
#pragma unroll
            for (int mf = 0; mf < 4; mf++) {
                int rb = wm * 64 + mf * 16;
                a[mf][0] = f2tf32(Au[(rb + lr) * PITCH + kk * 8 + lc]);
                a[mf][1] = f2tf32(Au[(rb + lr + 8) * PITCH + kk * 8 + lc]);
                a[mf][2] = f2tf32(Au[(rb + lr) * PITCH + kk * 8 + lc + 4]);
                a[mf][3] = f2tf32(Au[(rb + lr + 8) * PITCH + kk * 8 + lc + 4]);
            }
#pragma unroll
            for (int nf = 0; nf < 8; nf++) {
                int nb = wn * 64 + nf * 8 + lr;
                b[nf][0] = f2tf32(Bu[nb * PITCH + kk * 8 + lc]);
                b[nf][1] = f2tf32(Bu[nb * PITCH + kk * 8 + lc + 4]);
            }
#pragma unroll
            for (int mf = 0; mf < 4; mf++)
#pragma unroll
                for (int nf = 0; nf < 8; nf++)
                    mma_tf32(c[mf][nf], a[mf], b[nf]);
        }
    }

    // Epilogue: C-frag (r, 2lc) / (r+8, 2lc) float2 stores + bias
#pragma unroll
    for (int mf = 0; mf < 4; mf++) {
#pragma unroll
        for (int h = 0; h < 2; h++) {
            const int row = m0 + wm * 64 + mf * 16 + lr + 8 * h;
#pragma unroll
            for (int nf = 0; nf < 8; nf++) {
                const int col = n0 + wn * 64 + nf * 8 + 2 * lc;
                float v0 = c[mf][nf][2 * h + 0] + bias[col];
                float v1 = c[mf][nf][2 * h + 1] + bias[col + 1];
                size_t off;
                if (SPLIT) {
                    int bb = row >> 11, s = row & 2047;
                    int hh = col >> 6, d = col & 63;
                    off = (((size_t)(bb * NH + hh) * SS + s) * DK) + d;
                } else {
                    off = (size_t)row * DM + col;
                }
                *(float2*)(C + off) = make_float2(v0, v1);
            }
        }
    }
}

// ---------------------------------------------------------------------------
// Tensor-core flash attention (tf32 mma.sync), cp.async double-buffered K/V.
// Grid (S/128, B*H), 128 threads (4 warps). Warp owns 32 q-rows (2 m16 frags).
// Q frags register-resident (staged through K buffer 0 before the pipeline).
// K/V land RAW in smem via cp.async; fragments are rna-rounded in registers.
// Ksh pitch 68 (272B rows, 16B-aligned), Vsh pitch 72 (conflict-free PV
// B-frag reads: bank = lc*8+lr = lane), Psh pitch 36 warp-private 32x32.
// ---------------------------------------------------------------------------
#define KP 68
#define VP 72
#define ATTN_SMEM_FLOATS (2 * 64 * KP + 2 * 64 * VP + 4 * 32 * PITCH)
#define ATTN_SMEM_BYTES  (ATTN_SMEM_FLOATS * 4)   // 90112 B

__global__ __launch_bounds__(128)
void attn_tc(const float* __restrict__ Qh, const float* __restrict__ Kh,
             const float* __restrict__ Vh, float* __restrict__ AO) {
    extern __shared__ float dynsm[];
    float* Kbuf = dynsm;                       // 2 x 64*68
    float* Vbuf = dynsm + 2 * 64 * KP;         // 2 x 64*72
    float* Psh  = dynsm + 2 * 64 * KP + 2 * 64 * VP;  // 4*32*36

    const int tid = threadIdx.x, lane = tid & 31, wid = tid >> 5;
    const int lr = lane >> 2, lc = lane & 3;
    const int bh = blockIdx.y;
    const int q0 = blockIdx.x * 128;
    const size_t base = (size_t)bh * SS * DK;
    const uint32_t sa = smem_u32(dynsm);
    const uint32_t sa_v = sa + (uint32_t)(2 * 64 * KP * 4);

    // ---- Stage Q (scaled by 1/sqrt(64), rna-rounded) into register frags ----
    uint32_t qa[2][8][4];
    for (int pass = 0; pass < 2; pass++) {
        __syncthreads();
#pragma unroll
        for (int i = 0; i < 8; i++) {
            int idx = i * 128 + tid, row = idx >> 4, f4 = (idx & 15) * 4;
            float4 qv = *(const float4*)(Qh + base +
                        (size_t)(q0 + pass * 64 + row) * DK + f4);
            uint32_t* d = (uint32_t*)&Kbuf[row * KP + f4];
            d[0] = f2tf32(qv.x * 0.125f); d[1] = f2tf32(qv.y * 0.125f);
            d[2] = f2tf32(qv.z * 0.125f); d[3] = f2tf32(qv.w * 0.125f);
        }
        __syncthreads();
        if ((wid >> 1) == pass) {
            const uint32_t* Ku = (const uint32_t*)Kbuf;
            const int rb0 = (wid & 1) * 32;
#pragma unroll
            for (int mf = 0; mf < 2; mf++) {
                int rb = rb0 + mf * 16;
#pragma unroll
                for (int kk = 0; kk < 8; kk++) {
                    qa[mf][kk][0] = Ku[(rb + lr) * KP + kk * 8 + lc];
                    qa[mf][kk][1] = Ku[(rb + lr + 8) * KP + kk * 8 + lc];
                    qa[mf][kk][2] = Ku[(rb + lr) * KP + kk * 8 + lc + 4];
                    qa[mf][kk][3] = Ku[(rb + lr + 8) * KP + kk * 8 + lc + 4];
                }
            }
        }
    }
    __syncthreads();   // Q staging fully done before cp.async overwrites Kbuf

    float o[2][8][4];
#pragma unroll
    for (int mf = 0; mf < 2; mf++)
#pragma unroll
        for (int nf = 0; nf < 8; nf++)
#pragma unroll
            for (int r = 0; r < 4; r++) o[mf][nf][r] = 0.f;
    float mrow[2][2] = {{-1e30f, -1e30f}, {-1e30f, -1e30f}};
    float lrow[2][2] = {{0.f, 0.f}, {0.f, 0.f}};

    uint32_t* Pw = (uint32_t*)(Psh + wid * 32 * PITCH);

    // K/V tile load: 64 rows x 64 floats each; 8 float4s per thread per tensor
#define ATTN_LOAD_TILE(st, t) do {                                            \
    const size_t _r0 = base + (size_t)(t) * 64 * DK;                          \
    _Pragma("unroll")                                                         \
    for (int _i = 0; _i < 8; _i++) {                                          \
        int _idx = _i * 128 + tid, _row = _idx >> 4, _c4 = (_idx & 15) * 4;   \
        cp16(sa + (uint32_t)((((st) * 64 + _row) * KP + _c4) * 4),            \
             Kh + _r0 + (size_t)_row * DK + _c4);                             \
        cp16(sa_v + (uint32_t)((((st) * 64 + _row) * VP + _c4) * 4),          \
             Vh + _r0 + (size_t)_row * DK + _c4);                             \
    }                                                                         \
} while (0)

    ATTN_LOAD_TILE(0, 0); CP_COMMIT();

    const int NT = SS / 64;
    for (int t = 0; t < NT; t++) {
        if (t + 1 < NT) {
            ATTN_LOAD_TILE((t + 1) & 1, t + 1);
            CP_COMMIT();
            CP_WAIT1();
        } else {
            CP_WAIT0();
        }
        __syncthreads();

        const float* Kst = Kbuf + (t & 1) * 64 * KP;
        const float* Vst = Vbuf + (t & 1) * 64 * VP;

        // ---- S = Q @ K^T ----
        float s[2][8][4];
#pragma unroll
        for (int mf = 0; mf < 2; mf++)
#pragma unroll
            for (int nf = 0; nf < 8; nf++)
#pragma unroll
                for (int r = 0; r < 4; r++) s[mf][nf][r] = 0.f;
#pragma unroll
        for (int kk = 0; kk < 8; kk++) {
            uint32_t b[8][2];
#pragma unroll
            for (int nf = 0; nf < 8; nf++) {
                int nb = nf * 8 + lr;
                b[nf][0] = f2tf32(Kst[nb * KP + kk * 8 + lc]);
                b[nf][1] = f2tf32(Kst[nb * KP + kk * 8 + lc + 4]);
            }
#pragma unroll
            for (int mf = 0; mf < 2; mf++)
#pragma unroll
                for (int nf = 0; nf < 8; nf++)
                    mma_tf32(s[mf][nf], qa[mf][kk], b[nf]);
        }

        // ---- Online softmax (rows r / r+8 per m-frag; quad covers 64 cols) ----
#pragma unroll
        for (int mf = 0; mf < 2; mf++) {
#pragma unroll
            for (int h = 0; h < 2; h++) {
                float tm = -1e30f;
#pragma unroll
                for (int nf = 0; nf < 8; nf++)
                    tm = fmaxf(tm, fmaxf(s[mf][nf][2 * h], s[mf][nf][2 * h + 1]));
                tm = fmaxf(tm, __shfl_xor_sync(0xffffffffu, tm, 1));
                tm = fmaxf(tm, __shfl_xor_sync(0xffffffffu, tm, 2));
                float mn = fmaxf(mrow[mf][h], tm);
                float corr = __expf(mrow[mf][h] - mn);
                mrow[mf][h] = mn;
                float rs = 0.f;
#pragma unroll
                for (int nf = 0; nf < 8; nf++) {
                    float p0 = __expf(s[mf][nf][2 * h] - mn);
                    float p1 = __expf(s[mf][nf][2 * h + 1] - mn);
                    s[mf][nf][2 * h] = p0; s[mf][nf][2 * h + 1] = p1;
                    rs += p0 + p1;
                    o[mf][nf][2 * h] *= corr; o[mf][nf][2 * h + 1] *= corr;
                }
                rs += __shfl_xor_sync(0xffffffffu, rs, 1);
                rs += __shfl_xor_sync(0xffffffffu, rs, 2);
                lrow[mf][h] = lrow[mf][h] * corr + rs;
            }
        }

        // ---- O += P @ V, two 32-key halves (P slice is 32x32, pitch 36) ----
#pragma unroll
        for (int half = 0; half < 2; half++) {
            __syncwarp();
#pragma unroll
            for (int mf = 0; mf < 2; mf++)
#pragma unroll
                for (int nfl = 0; nfl < 4; nfl++) {
                    int nf = half * 4 + nfl;
                    int r0 = mf * 16 + lr, col = nfl * 8 + 2 * lc;
                    Pw[r0 * PITCH + col]           = f2tf32(s[mf][nf][0]);
                    Pw[r0 * PITCH + col + 1]       = f2tf32(s[mf][nf][1]);
                    Pw[(r0 + 8) * PITCH + col]     = f2tf32(s[mf][nf][2]);
                    Pw[(r0 + 8) * PITCH + col + 1] = f2tf32(s[mf][nf][3]);
                }
            __syncwarp();
#pragma unroll
            for (int kk = 0; kk < 4; kk++) {
                uint32_t a[2][4], b[8][2];
#pragma unroll
                for (int mf = 0; mf < 2; mf++) {
                    int rb = mf * 16;
                    a[mf][0] = Pw[(rb + lr) * PITCH + kk * 8 + lc];
                    a[mf][1] = Pw[(rb + lr + 8) * PITCH + kk * 8 + lc];
                    a[mf][2] = Pw[(rb + lr) * PITCH + kk * 8 + lc + 4];
                    a[mf][3] = Pw[(rb + lr + 8) * PITCH + kk * 8 + lc + 4];
                }
                const int krow = half * 32 + kk * 8;
#pragma unroll
                for (int nf = 0; nf < 8; nf++) {
                    b[nf][0] = f2tf32(Vst[(krow + lc) * VP + nf * 8 + lr]);
                    b[nf][1] = f2tf32(Vst[(krow + lc + 4) * VP + nf * 8 + lr]);
                }
#pragma unroll
                for (int mf = 0; mf < 2; mf++)
#pragma unroll
                    for (int nf = 0; nf < 8; nf++)
                        mma_tf32(o[mf][nf], a[mf], b[nf]);
            }
        }
        __syncthreads();   // tile fully consumed before cp.async reuses buffer
    }

    // ---- Epilogue: write AO [B,S,DM] (raw fp32; out-proj rounds fragments) ----
    const int bb = bh >> 4, hh = bh & 15;
#pragma unroll
    for (int mf = 0; mf < 2; mf++) {
#pragma unroll
        for (int h = 0; h < 2; h++) {
            float inv = 1.f / lrow[mf][h];
            int row = q0 + wid * 32 + mf * 16 + lr + 8 * h;
            float* dst = AO + ((size_t)bb * SS + row) * DM + hh * DK;
#pragma unroll
            for (int nf = 0; nf < 8; nf++) {
                int d = nf * 8 + 2 * lc;
                *(float2*)(dst + d) = make_float2(o[mf][nf][2 * h] * inv,
                                                  o[mf][nf][2 * h + 1] * inv);
            }
        }
    }
}

// ---------------------------------------------------------------------------
// Launch: batched QKV projections -> attention -> output projection
// ---------------------------------------------------------------------------
extern "C" void kernel_launch(void* const* d_in, const int* in_sizes, int n_in,
                              void* d_out, int out_size) {
    const float* q  = (const float*)d_in[0];
    const float* k  = (const float*)d_in[1];
    const float* v  = (const float*)d_in[2];
    const float* Wq = (const float*)d_in[3];
    const float* bq = (const float*)d_in[4];
    const float* Wk = (const float*)d_in[5];
    const float* bk = (const float*)d_in[6];
    const float* Wv = (const float*)d_in[7];
    const float* bv = (const float*)d_in[8];
    const float* Wo = (const float*)d_in[9];
    const float* bo = (const float*)d_in[10];

    void* p;
    cudaGetSymbolAddress(&p, g_Qh); float* Qh = (float*)p;
    cudaGetSymbolAddress(&p, g_Kh); float* Kh = (float*)p;
    cudaGetSymbolAddress(&p, g_Vh); float* Vh = (float*)p;
    cudaGetSymbolAddress(&p, g_AO); float* AO = (float*)p;

    cudaFuncSetAttribute(gemm_tc<true>,  cudaFuncAttributeMaxDynamicSharedMemorySize,
                         GEMM_SMEM_BYTES);
    cudaFuncSetAttribute(gemm_tc<false>, cudaFuncAttributeMaxDynamicSharedMemorySize,
                         GEMM_SMEM_BYTES);
    cudaFuncSetAttribute(attn_tc, cudaFuncAttributeMaxDynamicSharedMemorySize,
                         ATTN_SMEM_BYTES);

    dim3 gg3(DM / 128, MROWS / 128, 3);   // (8, 64, 3)
    gemm_tc<true><<<gg3, 128, GEMM_SMEM_BYTES>>>(q, k, v, Wq, Wk, Wv,
                                                 bq, bk, bv, Qh, Kh, Vh);

    attn_tc<<<dim3(SS / 128, MB * NH), 128, ATTN_SMEM_BYTES>>>(Qh, Kh, Vh, AO);

    dim3 gg1(DM / 128, MROWS / 128, 1);
    gemm_tc<false><<<gg1, 128, GEMM_SMEM_BYTES>>>(AO, AO, AO, Wo, Wo, Wo,
                                                  bo, bo, bo, (float*)d_out,
                                                  (float*)d_out, (float*)d_out);
}